// round 3
// baseline (speedup 1.0000x reference)
#include <cuda_runtime.h>
#include <math.h>

#define LAYERS 30
#define B_SZ 4
#define TLEN 32000
#define TT 64
#define NTILES (B_SZ * (TLEN / TT))   /* 2000 */
#define CH 64
#define GCH 128
#define CCH 80

/* packed per-layer weight blob (floats), all matrices transposed to [c][o] */
#define LAYER_WSZ 35072
#define OFF_WT1   8192
#define OFF_WTC   16384
#define OFF_WZ    26624
#define OFF_BCONV 34816
#define OFF_BSK   34944
#define OFF_BOUT  35008

typedef unsigned long long u64;

/* scratch (device globals: allocation-free rule) */
__device__ float g_h[2][B_SZ * CH * TLEN];      /* ping-pong residual */
__device__ float g_skips[B_SZ * CH * TLEN];
__device__ float g_c1[B_SZ * CCH * 400];
__device__ float g_c2[B_SZ * CCH * 4000];
__device__ float g_cup[B_SZ * CCH * TLEN];
__device__ float g_wt[LAYERS * LAYER_WSZ];
__device__ float g_wfirstT[256 * 64];
__device__ float g_wl1T[64 * 64];
__device__ float g_wl2T[64 * 256];

__device__ __forceinline__ float sig_f(float v) {
    return __fdividef(1.f, 1.f + __expf(-v));
}
__device__ __forceinline__ float tanh_f(float v) {
    return __fdividef(2.f, 1.f + __expf(-2.f * v)) - 1.f;
}

/* ---- packed f32x2 helpers (FFMA2: 2 MACs per fma-pipe issue) ---- */
__device__ __forceinline__ u64 pk2(float lo, float hi) {
    u64 r; asm("mov.b64 %0, {%1, %2};" : "=l"(r) : "f"(lo), "f"(hi)); return r;
}
__device__ __forceinline__ u64 dup2f(float v) { return pk2(v, v); }
__device__ __forceinline__ void fma2(u64& d, u64 a, u64 b) {
    asm("fma.rn.f32x2 %0, %1, %2, %0;" : "+l"(d) : "l"(a), "l"(b));
}
__device__ __forceinline__ void upk(float& lo, float& hi, u64 v) {
    asm("mov.b64 {%0, %1}, %2;" : "=f"(lo), "=f"(hi) : "l"(v));
}

/* ------------------- weight prep: transpose/pack, coalesced layer loads ----- */
__global__ void prep_layers_kernel(const float* __restrict__ conv_w,
                                   const float* __restrict__ conv_b,
                                   const float* __restrict__ cond_w,
                                   const float* __restrict__ out_w,
                                   const float* __restrict__ out_b,
                                   const float* __restrict__ skip_w,
                                   const float* __restrict__ skip_b) {
    int idx = blockIdx.x * blockDim.x + threadIdx.x;
    if (idx >= LAYERS * LAYER_WSZ) return;
    int l = idx / LAYER_WSZ;
    int j = idx % LAYER_WSZ;
    float v;
    if (j < OFF_WT1) {                       /* wt0[c][o] : delayed tap */
        int c = j >> 7, o = j & 127;
        v = conv_w[((l * 128 + o) * 64 + c) * 2 + 0];
    } else if (j < OFF_WTC) {                /* wt1[c][o] : current tap */
        int jj = j - OFF_WT1; int c = jj >> 7, o = jj & 127;
        v = conv_w[((l * 128 + o) * 64 + c) * 2 + 1];
    } else if (j < OFF_WZ) {                 /* wtc[c][o] : cond */
        int jj = j - OFF_WTC; int c = jj >> 7, o = jj & 127;
        v = cond_w[(l * 128 + o) * 80 + c];
    } else if (j < OFF_BCONV) {              /* wz[c][o2] : skip(0..63)|out(64..127) */
        int jj = j - OFF_WZ; int c = jj >> 7, o2 = jj & 127;
        v = (o2 < 64) ? skip_w[(l * 64 + o2) * 64 + c]
                      : out_w[(l * 64 + (o2 - 64)) * 64 + c];
    } else if (j < OFF_BSK) {
        v = conv_b[l * 128 + (j - OFF_BCONV)];
    } else if (j < OFF_BOUT) {
        v = skip_b[l * 64 + (j - OFF_BSK)];
    } else {
        v = out_b[l * 64 + (j - OFF_BOUT)];
    }
    g_wt[idx] = v;
}

__global__ void prep_firstlast_kernel(const float* __restrict__ first_w,
                                      const float* __restrict__ last1_w,
                                      const float* __restrict__ last2_w) {
    int idx = blockIdx.x * blockDim.x + threadIdx.x;
    if (idx < 16384) {                                   /* firstT[c][o], c<256,o<64 */
        int c = idx >> 6, o = idx & 63;
        g_wfirstT[idx] = first_w[o * 256 + c];
    } else if (idx < 16384 + 4096) {                     /* l1T[c][o] 64x64 */
        int jj = idx - 16384; int c = jj >> 6, o = jj & 63;
        g_wl1T[jj] = last1_w[o * 64 + c];
    } else if (idx < 16384 + 4096 + 16384) {             /* l2T[c][o] 64x256 */
        int jj = idx - 16384 - 4096; int c = jj >> 8, o = jj & 255;
        g_wl2T[jj] = last2_w[o * 64 + c];
    }
}

/* ------------------- conditioning network ---------------------------------- */
__global__ void convin_kernel(const float* __restrict__ cin,
                              const float* __restrict__ w) {
    int idx = blockIdx.x * blockDim.x + threadIdx.x;
    if (idx >= B_SZ * CCH * 400) return;
    int f = idx % 400;
    int o = (idx / 400) % CCH;
    int b = idx / (400 * CCH);
    const float* src = cin + (b * CCH) * 400 + f;
    float acc = 0.f;
#pragma unroll 8
    for (int c = 0; c < 80; ++c)
        acc += __ldg(&w[o * 80 + c]) * src[c * 400];
    g_c1[idx] = acc;
}

/* nearest-repeat by `scale` then depthwise conv (K=2*scale+1, zero pad scale) */
__global__ void upsample_kernel(const float* __restrict__ src,
                                const float* __restrict__ w,
                                float* __restrict__ dst,
                                int srcT, int dstT, int scale, int K) {
    int idx = blockIdx.x * blockDim.x + threadIdx.x;
    if (idx >= B_SZ * CCH * dstT) return;
    int t = idx % dstT;
    int ch = (idx / dstT) % CCH;
    int b = idx / (dstT * CCH);
    const float* s = src + (b * CCH + ch) * srcT;
    int base = t - scale;
    float acc = 0.f;
    for (int j = 0; j < K; ++j) {
        int u = base + j;
        if (u >= 0 && u < dstT) acc += __ldg(&w[j]) * s[u / scale];
    }
    dst[idx] = acc;
}

/* ------------------- first 1x1 conv: h = first_w @ x + b ------------------- */
__global__ void __launch_bounds__(256) first_kernel(const float* __restrict__ x,
                                                    const float* __restrict__ first_b) {
    extern __shared__ float sm[];
    float* xs = sm;            /* [256][64] */
    float* wf = sm + 16384;    /* wfT[c][o] 256x64 */
    for (int i = threadIdx.x; i < 16384 / 4; i += blockDim.x)
        ((float4*)wf)[i] = ((const float4*)g_wfirstT)[i];

    int to = threadIdx.x & 15, oo = threadIdx.x >> 4;
    int tb = to * 4, ob = oo * 4;

    for (int tile = blockIdx.x; tile < NTILES; tile += gridDim.x) {
        int b = tile / (TLEN / TT);
        int t0 = (tile % (TLEN / TT)) * TT;
        __syncthreads();
        const float* xb = x + (size_t)b * 256 * TLEN;
        for (int i = threadIdx.x; i < 256 * (TT / 4); i += blockDim.x) {
            int c = i / (TT / 4), q = i % (TT / 4);
            ((float4*)xs)[c * (TT / 4) + q] =
                *(const float4*)&xb[c * TLEN + t0 + q * 4];
        }
        __syncthreads();

        /* 2 output-pairs x 4 times, packed */
        u64 acc[2][4];
#pragma unroll
        for (int op = 0; op < 2; ++op) {
            u64 bv = pk2(first_b[ob + 2 * op], first_b[ob + 2 * op + 1]);
#pragma unroll
            for (int ti = 0; ti < 4; ++ti) acc[op][ti] = bv;
        }
#pragma unroll 2
        for (int c = 0; c < 256; ++c) {
            float4 xv4 = *(const float4*)(xs + c * TT + tb);
            u64 xv[4] = {dup2f(xv4.x), dup2f(xv4.y), dup2f(xv4.z), dup2f(xv4.w)};
            ulonglong2 wv = *(const ulonglong2*)(wf + c * 64 + ob);
            u64 w2[2] = {wv.x, wv.y};
#pragma unroll
            for (int op = 0; op < 2; ++op)
#pragma unroll
                for (int ti = 0; ti < 4; ++ti)
                    fma2(acc[op][ti], w2[op], xv[ti]);
        }
        float* hb = g_h[0] + (size_t)b * CH * TLEN;
#pragma unroll
        for (int op = 0; op < 2; ++op) {
            float lo[4], hi[4];
#pragma unroll
            for (int ti = 0; ti < 4; ++ti) upk(lo[ti], hi[ti], acc[op][ti]);
            float4 v0; v0.x = lo[0]; v0.y = lo[1]; v0.z = lo[2]; v0.w = lo[3];
            float4 v1; v1.x = hi[0]; v1.y = hi[1]; v1.z = hi[2]; v1.w = hi[3];
            *(float4*)&hb[(ob + 2 * op) * TLEN + t0 + tb] = v0;
            *(float4*)&hb[(ob + 2 * op + 1) * TLEN + t0 + tb] = v1;
        }
    }
}

/* ------------------- fused WaveNet residual layer -------------------------- */
__global__ void __launch_bounds__(256) layer_kernel(int l, int d, int hin, int first_layer) {
    extern __shared__ float sm[];
    float* sw = sm;                          /* 35072 packed weights */
    float* sh_cur = sm + LAYER_WSZ;          /* [64][TT] */
    float* sh_del = sh_cur + CH * TT;        /* [64][TT] */
    float* sc = sh_del + CH * TT;            /* [80][TT] */
    float* sg = sc + CCH * TT;               /* [128][TT]; rows 0..63 reused for z */

    const float* wt0 = sw;
    const float* wt1 = sw + OFF_WT1;
    const float* wtc = sw + OFF_WTC;
    const float* wz  = sw + OFF_WZ;
    const float* bconv = sw + OFF_BCONV;
    const float* bsk = sw + OFF_BSK;
    const float* bout = sw + OFF_BOUT;

    const float* wsrc = g_wt + (size_t)l * LAYER_WSZ;
    for (int i = threadIdx.x; i < LAYER_WSZ / 4; i += blockDim.x)
        ((float4*)sw)[i] = ((const float4*)wsrc)[i];

    const float* h_in = g_h[hin];
    float* h_out = g_h[hin ^ 1];

    int to = threadIdx.x & 15;   /* 16 time groups of 4 */
    int oo = threadIdx.x >> 4;   /* 16 out groups of 8  */
    int tb = to * 4, ob = oo * 8;

    for (int tile = blockIdx.x; tile < NTILES; tile += gridDim.x) {
        int b = tile / (TLEN / TT);
        int t0 = (tile % (TLEN / TT)) * TT;
        __syncthreads();   /* protect smem from previous iteration readers */

        const float* hb = h_in + (size_t)b * CH * TLEN;
        for (int i = threadIdx.x; i < CH * (TT / 4); i += blockDim.x) {
            int c = i / (TT / 4), q = i % (TT / 4);
            ((float4*)sh_cur)[c * (TT / 4) + q] =
                *(const float4*)&hb[c * TLEN + t0 + q * 4];
        }
        for (int i = threadIdx.x; i < CH * TT; i += blockDim.x) {
            int c = i >> 6, tt = i & 63;
            int t = t0 + tt - d;
            sh_del[c * TT + tt] = (t >= 0) ? hb[c * TLEN + t] : 0.f;
        }
        const float* cb = g_cup + (size_t)b * CCH * TLEN;
        for (int i = threadIdx.x; i < CCH * (TT / 4); i += blockDim.x) {
            int c = i / (TT / 4), q = i % (TT / 4);
            ((float4*)sc)[c * (TT / 4) + q] =
                *(const float4*)&cb[c * TLEN + t0 + q * 4];
        }
        __syncthreads();

        /* ---- gate GEMM: g[128][TT] = W0*h(t-d) + W1*h(t) + Wc*c + b ----
           4 output-pairs x 4 times, packed f32x2 */
        u64 acc[4][4];
#pragma unroll
        for (int op = 0; op < 4; ++op) {
            u64 bv = pk2(bconv[ob + 2 * op], bconv[ob + 2 * op + 1]);
#pragma unroll
            for (int ti = 0; ti < 4; ++ti) acc[op][ti] = bv;
        }
#pragma unroll 2
        for (int c = 0; c < 64; ++c) {
            float4 hd4 = *(const float4*)(sh_del + c * TT + tb);
            float4 hc4 = *(const float4*)(sh_cur + c * TT + tb);
            u64 hd[4] = {dup2f(hd4.x), dup2f(hd4.y), dup2f(hd4.z), dup2f(hd4.w)};
            u64 hc[4] = {dup2f(hc4.x), dup2f(hc4.y), dup2f(hc4.z), dup2f(hc4.w)};
            ulonglong2 w0a = *(const ulonglong2*)(wt0 + c * 128 + ob);
            ulonglong2 w0b = *(const ulonglong2*)(wt0 + c * 128 + ob + 4);
            ulonglong2 w1a = *(const ulonglong2*)(wt1 + c * 128 + ob);
            ulonglong2 w1b = *(const ulonglong2*)(wt1 + c * 128 + ob + 4);
            u64 w0[4] = {w0a.x, w0a.y, w0b.x, w0b.y};
            u64 w1[4] = {w1a.x, w1a.y, w1b.x, w1b.y};
#pragma unroll
            for (int op = 0; op < 4; ++op)
#pragma unroll
                for (int ti = 0; ti < 4; ++ti) {
                    fma2(acc[op][ti], w0[op], hd[ti]);
                    fma2(acc[op][ti], w1[op], hc[ti]);
                }
        }
#pragma unroll 2
        for (int c = 0; c < 80; ++c) {
            float4 cv4 = *(const float4*)(sc + c * TT + tb);
            u64 cv[4] = {dup2f(cv4.x), dup2f(cv4.y), dup2f(cv4.z), dup2f(cv4.w)};
            ulonglong2 wa = *(const ulonglong2*)(wtc + c * 128 + ob);
            ulonglong2 wb = *(const ulonglong2*)(wtc + c * 128 + ob + 4);
            u64 w2[4] = {wa.x, wa.y, wb.x, wb.y};
#pragma unroll
            for (int op = 0; op < 4; ++op)
#pragma unroll
                for (int ti = 0; ti < 4; ++ti)
                    fma2(acc[op][ti], w2[op], cv[ti]);
        }
#pragma unroll
        for (int op = 0; op < 4; ++op) {
            float lo[4], hi[4];
#pragma unroll
            for (int ti = 0; ti < 4; ++ti) upk(lo[ti], hi[ti], acc[op][ti]);
            float4 v0; v0.x = lo[0]; v0.y = lo[1]; v0.z = lo[2]; v0.w = lo[3];
            float4 v1; v1.x = hi[0]; v1.y = hi[1]; v1.z = hi[2]; v1.w = hi[3];
            *(float4*)(sg + (ob + 2 * op) * TT + tb) = v0;
            *(float4*)(sg + (ob + 2 * op + 1) * TT + tb) = v1;
        }
        __syncthreads();

        /* ---- z = tanh(a) * sigmoid(b), in place over rows 0..63 ---- */
        {
            int o = threadIdx.x >> 2;
            int ts = (threadIdx.x & 3) * 16;
#pragma unroll
            for (int k = 0; k < 16; k += 4) {
                float4 a4 = *(const float4*)(sg + o * TT + ts + k);
                float4 b4 = *(const float4*)(sg + (o + 64) * TT + ts + k);
                float4 z4;
                z4.x = tanh_f(a4.x) * sig_f(b4.x);
                z4.y = tanh_f(a4.y) * sig_f(b4.y);
                z4.z = tanh_f(a4.z) * sig_f(b4.z);
                z4.w = tanh_f(a4.w) * sig_f(b4.w);
                *(float4*)(sg + o * TT + ts + k) = z4;
            }
        }
        __syncthreads();

        /* ---- skip/out GEMM: [skip;out][128] x z[64], packed ---- */
#pragma unroll
        for (int op = 0; op < 4; ++op) {
            int o2 = ob + 2 * op;
            u64 bv = (o2 < 64) ? pk2(bsk[o2], bsk[o2 + 1])
                               : pk2(bout[o2 - 64], bout[o2 - 63]);
#pragma unroll
            for (int ti = 0; ti < 4; ++ti) acc[op][ti] = bv;
        }
#pragma unroll 2
        for (int c = 0; c < 64; ++c) {
            float4 zv4 = *(const float4*)(sg + c * TT + tb);
            u64 zv[4] = {dup2f(zv4.x), dup2f(zv4.y), dup2f(zv4.z), dup2f(zv4.w)};
            ulonglong2 wa = *(const ulonglong2*)(wz + c * 128 + ob);
            ulonglong2 wb = *(const ulonglong2*)(wz + c * 128 + ob + 4);
            u64 w2[4] = {wa.x, wa.y, wb.x, wb.y};
#pragma unroll
            for (int op = 0; op < 4; ++op)
#pragma unroll
                for (int ti = 0; ti < 4; ++ti)
                    fma2(acc[op][ti], w2[op], zv[ti]);
        }

        if (ob < 64) {  /* skip accumulation */
            float* skb = g_skips + (size_t)b * CH * TLEN;
#pragma unroll
            for (int op = 0; op < 4; ++op) {
                float lo[4], hi[4];
#pragma unroll
                for (int ti = 0; ti < 4; ++ti) upk(lo[ti], hi[ti], acc[op][ti]);
                float* p0 = skb + (ob + 2 * op) * TLEN + t0 + tb;
                float* p1 = skb + (ob + 2 * op + 1) * TLEN + t0 + tb;
                float4 v0; v0.x = lo[0]; v0.y = lo[1]; v0.z = lo[2]; v0.w = lo[3];
                float4 v1; v1.x = hi[0]; v1.y = hi[1]; v1.z = hi[2]; v1.w = hi[3];
                if (!first_layer) {
                    float4 o0 = *(const float4*)p0;
                    float4 o1 = *(const float4*)p1;
                    v0.x += o0.x; v0.y += o0.y; v0.z += o0.z; v0.w += o0.w;
                    v1.x += o1.x; v1.y += o1.y; v1.z += o1.z; v1.w += o1.w;
                }
                *(float4*)p0 = v0;
                *(float4*)p1 = v1;
            }
        } else {        /* residual update h_out = h_in + out */
            float* hob = h_out + (size_t)b * CH * TLEN;
#pragma unroll
            for (int op = 0; op < 4; ++op) {
                float lo[4], hi[4];
#pragma unroll
                for (int ti = 0; ti < 4; ++ti) upk(lo[ti], hi[ti], acc[op][ti]);
                int o0 = ob - 64 + 2 * op;
                float4 r0 = *(const float4*)(sh_cur + o0 * TT + tb);
                float4 r1 = *(const float4*)(sh_cur + (o0 + 1) * TT + tb);
                float4 v0; v0.x = lo[0] + r0.x; v0.y = lo[1] + r0.y;
                v0.z = lo[2] + r0.z; v0.w = lo[3] + r0.w;
                float4 v1; v1.x = hi[0] + r1.x; v1.y = hi[1] + r1.y;
                v1.z = hi[2] + r1.z; v1.w = hi[3] + r1.w;
                *(float4*)&hob[o0 * TLEN + t0 + tb] = v0;
                *(float4*)&hob[(o0 + 1) * TLEN + t0 + tb] = v1;
            }
        }
    }
}

/* ------------------- last: relu -> 1x1(64) -> relu -> 1x1(256) ------------- */
__global__ void __launch_bounds__(256) last_kernel(const float* __restrict__ l1b,
                                                   const float* __restrict__ l2b,
                                                   float* __restrict__ out) {
    extern __shared__ float sm[];
    float* w1 = sm;             /* 64x64  l1T[c][o] */
    float* w2 = sm + 4096;      /* 64x256 l2T[c][o] */
    float* sk = sm + 20480;     /* [64][TT] */
    float* o1 = sm + 24576;     /* [64][TT] */

    for (int i = threadIdx.x; i < 4096 / 4; i += blockDim.x)
        ((float4*)w1)[i] = ((const float4*)g_wl1T)[i];
    for (int i = threadIdx.x; i < 16384 / 4; i += blockDim.x)
        ((float4*)w2)[i] = ((const float4*)g_wl2T)[i];

    int to = threadIdx.x & 15, oo = threadIdx.x >> 4;
    int tb = to * 4;

    for (int tile = blockIdx.x; tile < NTILES; tile += gridDim.x) {
        int b = tile / (TLEN / TT);
        int t0 = (tile % (TLEN / TT)) * TT;
        __syncthreads();
        const float* skb = g_skips + (size_t)b * CH * TLEN;
        for (int i = threadIdx.x; i < CH * (TT / 4); i += blockDim.x) {
            int c = i / (TT / 4), q = i % (TT / 4);
            float4 v = *(const float4*)&skb[c * TLEN + t0 + q * 4];
            v.x = fmaxf(v.x, 0.f); v.y = fmaxf(v.y, 0.f);
            v.z = fmaxf(v.z, 0.f); v.w = fmaxf(v.w, 0.f);
            ((float4*)sk)[c * (TT / 4) + q] = v;
        }
        __syncthreads();

        /* GEMM1: 64x64, relu */
        {
            int ob = oo * 4;
            u64 acc[2][4];
#pragma unroll
            for (int op = 0; op < 2; ++op) {
                u64 bv = pk2(l1b[ob + 2 * op], l1b[ob + 2 * op + 1]);
#pragma unroll
                for (int ti = 0; ti < 4; ++ti) acc[op][ti] = bv;
            }
#pragma unroll 2
            for (int c = 0; c < 64; ++c) {
                float4 xv4 = *(const float4*)(sk + c * TT + tb);
                u64 xv[4] = {dup2f(xv4.x), dup2f(xv4.y), dup2f(xv4.z), dup2f(xv4.w)};
                ulonglong2 wv = *(const ulonglong2*)(w1 + c * 64 + ob);
                u64 wp[2] = {wv.x, wv.y};
#pragma unroll
                for (int op = 0; op < 2; ++op)
#pragma unroll
                    for (int ti = 0; ti < 4; ++ti)
                        fma2(acc[op][ti], wp[op], xv[ti]);
            }
#pragma unroll
            for (int op = 0; op < 2; ++op) {
                float lo[4], hi[4];
#pragma unroll
                for (int ti = 0; ti < 4; ++ti) upk(lo[ti], hi[ti], acc[op][ti]);
                float4 v0, v1;
                v0.x = fmaxf(lo[0], 0.f); v0.y = fmaxf(lo[1], 0.f);
                v0.z = fmaxf(lo[2], 0.f); v0.w = fmaxf(lo[3], 0.f);
                v1.x = fmaxf(hi[0], 0.f); v1.y = fmaxf(hi[1], 0.f);
                v1.z = fmaxf(hi[2], 0.f); v1.w = fmaxf(hi[3], 0.f);
                *(float4*)(o1 + (ob + 2 * op) * TT + tb) = v0;
                *(float4*)(o1 + (ob + 2 * op + 1) * TT + tb) = v1;
            }
        }
        __syncthreads();

        /* GEMM2: 256x64, two halves of 128 outputs */
        float* ob_out = out + (size_t)b * 256 * TLEN;
#pragma unroll
        for (int half = 0; half < 2; ++half) {
            int ob2 = half * 128 + oo * 8;
            u64 acc[4][4];
#pragma unroll
            for (int op = 0; op < 4; ++op) {
                u64 bv = pk2(l2b[ob2 + 2 * op], l2b[ob2 + 2 * op + 1]);
#pragma unroll
                for (int ti = 0; ti < 4; ++ti) acc[op][ti] = bv;
            }
#pragma unroll 2
            for (int c = 0; c < 64; ++c) {
                float4 zv4 = *(const float4*)(o1 + c * TT + tb);
                u64 zv[4] = {dup2f(zv4.x), dup2f(zv4.y), dup2f(zv4.z), dup2f(zv4.w)};
                ulonglong2 wa = *(const ulonglong2*)(w2 + c * 256 + ob2);
                ulonglong2 wb = *(const ulonglong2*)(w2 + c * 256 + ob2 + 4);
                u64 wp[4] = {wa.x, wa.y, wb.x, wb.y};
#pragma unroll
                for (int op = 0; op < 4; ++op)
#pragma unroll
                    for (int ti = 0; ti < 4; ++ti)
                        fma2(acc[op][ti], wp[op], zv[ti]);
            }
#pragma unroll
            for (int op = 0; op < 4; ++op) {
                float lo[4], hi[4];
#pragma unroll
                for (int ti = 0; ti < 4; ++ti) upk(lo[ti], hi[ti], acc[op][ti]);
                float4 v0; v0.x = lo[0]; v0.y = lo[1]; v0.z = lo[2]; v0.w = lo[3];
                float4 v1; v1.x = hi[0]; v1.y = hi[1]; v1.z = hi[2]; v1.w = hi[3];
                *(float4*)&ob_out[(ob2 + 2 * op) * TLEN + t0 + tb] = v0;
                *(float4*)&ob_out[(ob2 + 2 * op + 1) * TLEN + t0 + tb] = v1;
            }
        }
    }
}

/* --------------------------------------------------------------------------- */
extern "C" void kernel_launch(void* const* d_in, const int* in_sizes, int n_in,
                              void* d_out, int out_size) {
    const float* x        = (const float*)d_in[0];
    const float* c        = (const float*)d_in[1];
    const float* first_w  = (const float*)d_in[2];
    const float* first_b  = (const float*)d_in[3];
    const float* conv_w   = (const float*)d_in[4];
    const float* conv_b   = (const float*)d_in[5];
    const float* cond_w   = (const float*)d_in[6];
    const float* out_w    = (const float*)d_in[7];
    const float* out_b    = (const float*)d_in[8];
    const float* skip_w   = (const float*)d_in[9];
    const float* skip_b   = (const float*)d_in[10];
    const float* last1_w  = (const float*)d_in[11];
    const float* last1_b  = (const float*)d_in[12];
    const float* last2_w  = (const float*)d_in[13];
    const float* last2_b  = (const float*)d_in[14];
    const float* conv_in_w= (const float*)d_in[15];
    const float* up_w0    = (const float*)d_in[16];
    const float* up_w1    = (const float*)d_in[17];
    float* out = (float*)d_out;

    int dev = 0;
    cudaGetDevice(&dev);
    int sms = 148;
    cudaDeviceGetAttribute(&sms, cudaDevAttrMultiProcessorCount, dev);

    cudaFuncSetAttribute(first_kernel, cudaFuncAttributeMaxDynamicSharedMemorySize, 131072);
    cudaFuncSetAttribute(layer_kernel, cudaFuncAttributeMaxDynamicSharedMemorySize, 226304);
    cudaFuncSetAttribute(last_kernel,  cudaFuncAttributeMaxDynamicSharedMemorySize, 114688);

    /* weight prep */
    {
        int total = LAYERS * LAYER_WSZ;
        prep_layers_kernel<<<(total + 255) / 256, 256>>>(
            conv_w, conv_b, cond_w, out_w, out_b, skip_w, skip_b);
        prep_firstlast_kernel<<<(16384 + 4096 + 16384 + 255) / 256, 256>>>(
            first_w, last1_w, last2_w);
    }

    /* conditioning: 1x1 conv + two upsample stages */
    {
        int n1 = B_SZ * CCH * 400;
        convin_kernel<<<(n1 + 255) / 256, 256>>>(c, conv_in_w);

        float* c1p = nullptr; float* c2p = nullptr; float* cupp = nullptr;
        cudaGetSymbolAddress((void**)&c1p, g_c1);
        cudaGetSymbolAddress((void**)&c2p, g_c2);
        cudaGetSymbolAddress((void**)&cupp, g_cup);

        int n2 = B_SZ * CCH * 4000;
        upsample_kernel<<<(n2 + 255) / 256, 256>>>(c1p, up_w0, c2p, 400, 4000, 10, 21);
        int n3 = B_SZ * CCH * TLEN;
        upsample_kernel<<<(n3 + 255) / 256, 256>>>(c2p, up_w1, cupp, 4000, TLEN, 8, 17);
    }

    /* first conv */
    first_kernel<<<sms, 256, 131072>>>(x, first_b);

    /* 30 residual layers, ping-pong h */
    for (int l = 0; l < LAYERS; ++l) {
        int d = 1 << (l % 10);
        layer_kernel<<<sms, 256, 226304>>>(l, d, l & 1, l == 0 ? 1 : 0);
    }

    /* final projection */
    last_kernel<<<sms, 256, 114688>>>(last1_b, last2_b, out);
}

// round 5
// speedup vs baseline: 1.6431x; 1.6431x over previous
#include <cuda_runtime.h>
#include <cuda_bf16.h>
#include <math.h>
#include <stdint.h>

#define LAYERS 30
#define B_SZ 4
#define TLEN 32000
#define TT 64
#define NTILES (B_SZ * (TLEN / TT))
#define CH 64
#define CCH 80

/* SMEM layout (bytes). B1: 208 rows x 144B (64 bf16 + pad). B2: 64 rows. */
#define SM_B1H 0
#define SM_B1M 29952
#define SM_B2H 59904
#define SM_B2M 69120
#define SM_TOTAL 78336

typedef unsigned long long u64;
typedef uint32_t u32;

/* scratch (device globals: allocation-free rule) */
__device__ float g_h[2][B_SZ * CH * TLEN];
__device__ float g_skips[B_SZ * CH * TLEN];
__device__ float g_c1[B_SZ * CCH * 400];
__device__ float g_c2[B_SZ * CCH * 4000];
__device__ __nv_bfloat16 g_cbh[B_SZ * CCH * TLEN];
__device__ __nv_bfloat16 g_cbm[B_SZ * CCH * TLEN];
__device__ u32 g_gwh[LAYERS * 128 * 104];   /* gate W hi, interleaved rows, kpairs */
__device__ u32 g_gwm[LAYERS * 128 * 104];
__device__ u32 g_wzh[LAYERS * 128 * 32];    /* skip|out W hi, plain rows */
__device__ u32 g_wzm[LAYERS * 128 * 32];
__device__ float g_wfirstT[256 * 64];
__device__ float g_wl1T[64 * 64];
__device__ float g_wl2T[64 * 256];

__device__ __forceinline__ float sig_f(float v) { return __fdividef(1.f, 1.f + __expf(-v)); }
__device__ __forceinline__ float tanh_f(float v) { return __fdividef(2.f, 1.f + __expf(-2.f * v)) - 1.f; }
__device__ __forceinline__ u32 pkbf(float a, float b) {
    __nv_bfloat162 h = __floats2bfloat162_rn(a, b);
    return *reinterpret_cast<u32*>(&h);
}
__device__ __forceinline__ float bflo(float a) { return __bfloat162float(__float2bfloat16(a)); }

__device__ __forceinline__ u32 smem_u32(const void* p) {
    u32 a;
    asm("{ .reg .u64 t; cvta.to.shared.u64 t, %1; cvt.u32.u64 %0, t; }" : "=r"(a) : "l"(p));
    return a;
}
__device__ __forceinline__ void mma16816(float* d, const u32* a, const u32* b) {
    asm volatile("mma.sync.aligned.m16n8k16.row.col.f32.bf16.bf16.f32 "
        "{%0,%1,%2,%3}, {%4,%5,%6,%7}, {%8,%9}, {%0,%1,%2,%3};"
        : "+f"(d[0]), "+f"(d[1]), "+f"(d[2]), "+f"(d[3])
        : "r"(a[0]), "r"(a[1]), "r"(a[2]), "r"(a[3]), "r"(b[0]), "r"(b[1]));
}
__device__ __forceinline__ void ldmT_x4(u32* r, u32 addr) {
    asm volatile("ldmatrix.sync.aligned.m8n8.x4.trans.shared.b16 {%0,%1,%2,%3}, [%4];"
        : "=r"(r[0]), "=r"(r[1]), "=r"(r[2]), "=r"(r[3]) : "r"(addr));
}
__device__ __forceinline__ void ldmT_x2(u32* r, u32 addr) {
    asm volatile("ldmatrix.sync.aligned.m8n8.x2.trans.shared.b16 {%0,%1}, [%2];"
        : "=r"(r[0]), "=r"(r[1]) : "r"(addr));
}

/* f32x2 helpers for first/last kernels */
__device__ __forceinline__ u64 pk2(float lo, float hi) {
    u64 r; asm("mov.b64 %0, {%1, %2};" : "=l"(r) : "f"(lo), "f"(hi)); return r;
}
__device__ __forceinline__ u64 dup2f(float v) { return pk2(v, v); }
__device__ __forceinline__ void fma2(u64& d, u64 a, u64 b) {
    asm("fma.rn.f32x2 %0, %1, %2, %0;" : "+l"(d) : "l"(a), "l"(b));
}
__device__ __forceinline__ void upk(float& lo, float& hi, u64 v) {
    asm("mov.b64 {%0, %1}, %2;" : "=f"(lo), "=f"(hi) : "l"(v));
}

/* gate row interleave: band q rows 16q+i: i<8 -> a-ch 8q+i (orig row 8q+i),
   i>=8 -> b-ch 8q+(i-8) (orig row 64+8q+i-8) */
__device__ __forceinline__ int orig_gate_row(int r) {
    int q = r >> 4, i = r & 15;
    return (i < 8) ? (8 * q + i) : (64 + 8 * q + (i - 8));
}

/* ---------------- weight prep ---------------- */
__global__ void prep_gate_kernel(const float* __restrict__ conv_w,
                                 const float* __restrict__ cond_w) {
    int idx = blockIdx.x * blockDim.x + threadIdx.x;
    if (idx >= LAYERS * 128 * 104) return;
    int l = idx / (128 * 104), rem = idx % (128 * 104);
    int r = rem / 104, kp = rem % 104;
    int o = orig_gate_row(r);
    float w[2];
#pragma unroll
    for (int e = 0; e < 2; ++e) {
        int k = 2 * kp + e;
        if (k < 64)       w[e] = conv_w[((l * 128 + o) * 64 + k) * 2 + 0];
        else if (k < 128) w[e] = conv_w[((l * 128 + o) * 64 + (k - 64)) * 2 + 1];
        else              w[e] = cond_w[(l * 128 + o) * 80 + (k - 128)];
    }
    g_gwh[idx] = pkbf(w[0], w[1]);
    g_gwm[idx] = pkbf(w[0] - bflo(w[0]), w[1] - bflo(w[1]));
}

__global__ void prep_wz_kernel(const float* __restrict__ skip_w,
                               const float* __restrict__ out_w) {
    int idx = blockIdx.x * blockDim.x + threadIdx.x;
    if (idx >= LAYERS * 128 * 32) return;
    int l = idx / (128 * 32), rem = idx % (128 * 32);
    int r = rem / 32, kp = rem % 32;
    float w[2];
#pragma unroll
    for (int e = 0; e < 2; ++e) {
        int k = 2 * kp + e;
        w[e] = (r < 64) ? skip_w[(l * 64 + r) * 64 + k]
                        : out_w[(l * 64 + (r - 64)) * 64 + k];
    }
    g_wzh[idx] = pkbf(w[0], w[1]);
    g_wzm[idx] = pkbf(w[0] - bflo(w[0]), w[1] - bflo(w[1]));
}

__global__ void prep_firstlast_kernel(const float* __restrict__ first_w,
                                      const float* __restrict__ last1_w,
                                      const float* __restrict__ last2_w) {
    int idx = blockIdx.x * blockDim.x + threadIdx.x;
    if (idx < 16384) {
        int c = idx >> 6, o = idx & 63;
        g_wfirstT[idx] = first_w[o * 256 + c];
    } else if (idx < 16384 + 4096) {
        int jj = idx - 16384; int c = jj >> 6, o = jj & 63;
        g_wl1T[jj] = last1_w[o * 64 + c];
    } else if (idx < 16384 + 4096 + 16384) {
        int jj = idx - 16384 - 4096; int c = jj >> 8, o = jj & 255;
        g_wl2T[jj] = last2_w[o * 64 + c];
    }
}

/* ---------------- conditioning ---------------- */
__global__ void convin_kernel(const float* __restrict__ cin,
                              const float* __restrict__ w) {
    int idx = blockIdx.x * blockDim.x + threadIdx.x;
    if (idx >= B_SZ * CCH * 400) return;
    int f = idx % 400, o = (idx / 400) % CCH, b = idx / (400 * CCH);
    const float* src = cin + (b * CCH) * 400 + f;
    float acc = 0.f;
#pragma unroll 8
    for (int c = 0; c < 80; ++c) acc += __ldg(&w[o * 80 + c]) * src[c * 400];
    g_c1[idx] = acc;
}

__global__ void upsample1_kernel(const float* __restrict__ w) {
    int idx = blockIdx.x * blockDim.x + threadIdx.x;
    if (idx >= B_SZ * CCH * 4000) return;
    int t = idx % 4000, ch = (idx / 4000) % CCH, b = idx / (4000 * CCH);
    const float* s = g_c1 + (b * CCH + ch) * 400;
    int base = t - 10;
    float acc = 0.f;
    for (int j = 0; j < 21; ++j) {
        int u = base + j;
        if (u >= 0 && u < 4000) acc += __ldg(&w[j]) * s[u / 10];
    }
    g_c2[idx] = acc;
}

__global__ void upsample2_kernel(const float* __restrict__ w) {
    int idx = blockIdx.x * blockDim.x + threadIdx.x;
    if (idx >= B_SZ * CCH * TLEN) return;
    int t = idx % TLEN, ch = (idx / TLEN) % CCH, b = idx / (TLEN * CCH);
    const float* s = g_c2 + (b * CCH + ch) * 4000;
    int base = t - 8;
    float acc = 0.f;
    for (int j = 0; j < 17; ++j) {
        int u = base + j;
        if (u >= 0 && u < TLEN) acc += __ldg(&w[j]) * s[u / 8];
    }
    g_cbh[idx] = __float2bfloat16(acc);
    g_cbm[idx] = __float2bfloat16(acc - bflo(acc));
}

/* ---------------- first 1x1 conv (FFMA2) ---------------- */
__global__ void __launch_bounds__(256) first_kernel(const float* __restrict__ x,
                                                    const float* __restrict__ first_b) {
    extern __shared__ float sm[];
    float* xs = sm;
    float* wf = sm + 16384;
    for (int i = threadIdx.x; i < 16384 / 4; i += blockDim.x)
        ((float4*)wf)[i] = ((const float4*)g_wfirstT)[i];
    int to = threadIdx.x & 15, oo = threadIdx.x >> 4;
    int tb = to * 4, ob = oo * 4;
    for (int tile = blockIdx.x; tile < NTILES; tile += gridDim.x) {
        int b = tile / (TLEN / TT), t0 = (tile % (TLEN / TT)) * TT;
        __syncthreads();
        const float* xb = x + (size_t)b * 256 * TLEN;
        for (int i = threadIdx.x; i < 256 * (TT / 4); i += blockDim.x) {
            int c = i / (TT / 4), q = i % (TT / 4);
            ((float4*)xs)[c * (TT / 4) + q] = *(const float4*)&xb[c * TLEN + t0 + q * 4];
        }
        __syncthreads();
        u64 acc[2][4];
#pragma unroll
        for (int op = 0; op < 2; ++op) {
            u64 bv = pk2(first_b[ob + 2 * op], first_b[ob + 2 * op + 1]);
#pragma unroll
            for (int ti = 0; ti < 4; ++ti) acc[op][ti] = bv;
        }
#pragma unroll 2
        for (int c = 0; c < 256; ++c) {
            float4 xv4 = *(const float4*)(xs + c * TT + tb);
            u64 xv[4] = {dup2f(xv4.x), dup2f(xv4.y), dup2f(xv4.z), dup2f(xv4.w)};
            ulonglong2 wv = *(const ulonglong2*)(wf + c * 64 + ob);
            u64 w2[2] = {wv.x, wv.y};
#pragma unroll
            for (int op = 0; op < 2; ++op)
#pragma unroll
                for (int ti = 0; ti < 4; ++ti) fma2(acc[op][ti], w2[op], xv[ti]);
        }
        float* hb = g_h[0] + (size_t)b * CH * TLEN;
#pragma unroll
        for (int op = 0; op < 2; ++op) {
            float lo[4], hi[4];
#pragma unroll
            for (int ti = 0; ti < 4; ++ti) upk(lo[ti], hi[ti], acc[op][ti]);
            float4 v0 = {lo[0], lo[1], lo[2], lo[3]};
            float4 v1 = {hi[0], hi[1], hi[2], hi[3]};
            *(float4*)&hb[(ob + 2 * op) * TLEN + t0 + tb] = v0;
            *(float4*)&hb[(ob + 2 * op + 1) * TLEN + t0 + tb] = v1;
        }
    }
}

/* ---------------- fused residual layer (mma.sync bf16 3-split) ------------- */
__global__ void __launch_bounds__(256, 1) layer_kernel(int l, int d, int hin, int first_layer,
        const float* __restrict__ conv_b, const float* __restrict__ skip_b,
        const float* __restrict__ out_b) {
    extern __shared__ char smc[];
    u32 sb = smem_u32(smc);
    int tid = threadIdx.x, w = tid >> 5, lane = tid & 31;
    int lq = lane >> 2, lr = lane & 3;

    /* --- load A fragments (weights) into registers, once per layer --- */
    u32 Ah[13][4], Am[13][4], Zh[4][4], Zm[4][4];
    {
        const u32* gh = g_gwh + ((size_t)l * 128 + 16 * w) * 104;
        const u32* gm = g_gwm + ((size_t)l * 128 + 16 * w) * 104;
#pragma unroll
        for (int ks = 0; ks < 13; ++ks) {
            int kp = 8 * ks + lr;
            Ah[ks][0] = gh[lq * 104 + kp];     Ah[ks][1] = gh[(8 + lq) * 104 + kp];
            Ah[ks][2] = gh[lq * 104 + kp + 4]; Ah[ks][3] = gh[(8 + lq) * 104 + kp + 4];
            Am[ks][0] = gm[lq * 104 + kp];     Am[ks][1] = gm[(8 + lq) * 104 + kp];
            Am[ks][2] = gm[lq * 104 + kp + 4]; Am[ks][3] = gm[(8 + lq) * 104 + kp + 4];
        }
        const u32* zh = g_wzh + ((size_t)l * 128 + 16 * w) * 32;
        const u32* zm = g_wzm + ((size_t)l * 128 + 16 * w) * 32;
#pragma unroll
        for (int ks = 0; ks < 4; ++ks) {
            int kp = 8 * ks + lr;
            Zh[ks][0] = zh[lq * 32 + kp];     Zh[ks][1] = zh[(8 + lq) * 32 + kp];
            Zh[ks][2] = zh[lq * 32 + kp + 4]; Zh[ks][3] = zh[(8 + lq) * 32 + kp + 4];
            Zm[ks][0] = zm[lq * 32 + kp];     Zm[ks][1] = zm[(8 + lq) * 32 + kp];
            Zm[ks][2] = zm[lq * 32 + kp + 4]; Zm[ks][3] = zm[(8 + lq) * 32 + kp + 4];
        }
    }
    int gch = 8 * w + lq;                       /* gate channel for this thread */
    float ba = conv_b[l * 128 + gch];
    float bb = conv_b[l * 128 + 64 + gch];
    int r1 = 16 * w + lq;                       /* skip/out row */
    float bs0 = (r1 < 64) ? skip_b[l * 64 + r1] : out_b[l * 64 + r1 - 64];
    float bs1 = (r1 < 64) ? skip_b[l * 64 + r1 + 8] : out_b[l * 64 + r1 - 56];

    const float* h_in = g_h[hin];
    float* h_out = g_h[hin ^ 1];
    u32 b1h_l4 = sb + SM_B1H + lane * 144;
    u32 b1m_l4 = sb + SM_B1M + lane * 144;
    u32 b1h_l2 = sb + SM_B1H + (lane & 15) * 144;
    u32 b1m_l2 = sb + SM_B1M + (lane & 15) * 144;
    u32 b2h_l4 = sb + SM_B2H + lane * 144;
    u32 b2m_l4 = sb + SM_B2M + lane * 144;
    int dal = (d & 3) == 0;                     /* float4 fast path allowed */

    for (int tile = blockIdx.x; tile < NTILES; tile += gridDim.x) {
        int b = tile / (TLEN / TT), t0 = (tile % (TLEN / TT)) * TT;
        const float* hb = h_in + (size_t)b * CH * TLEN;

        /* ---- build B1: rows 0..63 h(t-d), 64..127 h(t), 128..207 cond ---- */
        for (int i = tid; i < 1024; i += 256) {
            int r = i >> 3, g = i & 7;
            int ch = r & 63;
            int tt0 = t0 + g * 8 - ((r < 64) ? d : 0);
            const float* src = hb + (size_t)ch * TLEN;
            float v[8];
            if (tt0 >= 0 && (dal || r >= 64)) {
                float4 f0 = *(const float4*)(src + tt0);
                float4 f1 = *(const float4*)(src + tt0 + 4);
                v[0] = f0.x; v[1] = f0.y; v[2] = f0.z; v[3] = f0.w;
                v[4] = f1.x; v[5] = f1.y; v[6] = f1.z; v[7] = f1.w;
            } else {
#pragma unroll
                for (int e = 0; e < 8; ++e) {
                    int tt = tt0 + e;
                    v[e] = (tt >= 0) ? __ldg(src + tt) : 0.f;
                }
            }
            u32 hi[4], mi[4];
#pragma unroll
            for (int e = 0; e < 4; ++e) {
                float x0 = v[2 * e], x1 = v[2 * e + 1];
                hi[e] = pkbf(x0, x1);
                mi[e] = pkbf(x0 - bflo(x0), x1 - bflo(x1));
            }
            int off = r * 144 + g * 16;
            *(uint4*)(smc + SM_B1H + off) = make_uint4(hi[0], hi[1], hi[2], hi[3]);
            *(uint4*)(smc + SM_B1M + off) = make_uint4(mi[0], mi[1], mi[2], mi[3]);
        }
        for (int i = tid; i < 640; i += 256) {
            int r = i >> 3, g = i & 7;
            const uint4* s1 = (const uint4*)(g_cbh + ((size_t)(b * 80 + r)) * TLEN + t0);
            const uint4* s2 = (const uint4*)(g_cbm + ((size_t)(b * 80 + r)) * TLEN + t0);
            int off = (128 + r) * 144 + g * 16;
            *(uint4*)(smc + SM_B1H + off) = s1[g];
            *(uint4*)(smc + SM_B1M + off) = s2[g];
        }
        __syncthreads();

        /* ---- gate GEMM + activation, per 8-time n-tile ---- */
#pragma unroll 1
        for (int j = 0; j < 8; ++j) {
            float D0[4] = {0, 0, 0, 0}, D1[4] = {0, 0, 0, 0}, D2[4] = {0, 0, 0, 0};
            int tb = j * 16;
#pragma unroll
            for (int kk = 0; kk < 6; ++kk) {
                u32 bh[4], bm[4];
                ldmT_x4(bh, b1h_l4 + kk * 32 * 144 + tb);
                ldmT_x4(bm, b1m_l4 + kk * 32 * 144 + tb);
                mma16816(D0, Ah[2 * kk], bh);
                mma16816(D0, Ah[2 * kk + 1], bh + 2);
                mma16816(D1, Ah[2 * kk], bm);
                mma16816(D1, Ah[2 * kk + 1], bm + 2);
                mma16816(D2, Am[2 * kk], bh);
                mma16816(D2, Am[2 * kk + 1], bh + 2);
            }
            {
                u32 bh[2], bm[2];
                ldmT_x2(bh, b1h_l2 + 192 * 144 + tb);
                ldmT_x2(bm, b1m_l2 + 192 * 144 + tb);
                mma16816(D0, Ah[12], bh);
                mma16816(D1, Ah[12], bm);
                mma16816(D2, Am[12], bh);
            }
            float a0 = D0[0] + D1[0] + D2[0] + ba;
            float a1 = D0[1] + D1[1] + D2[1] + ba;
            float b0 = D0[2] + D1[2] + D2[2] + bb;
            float b1 = D0[3] + D1[3] + D2[3] + bb;
            float z0 = tanh_f(a0) * sig_f(b0);
            float z1 = tanh_f(a1) * sig_f(b1);
            int zoff = gch * 144 + (j * 8 + lr * 2) * 2;
            *(u32*)(smc + SM_B2H + zoff) = pkbf(z0, z1);
            *(u32*)(smc + SM_B2M + zoff) = pkbf(z0 - bflo(z0), z1 - bflo(z1));
        }
        __syncthreads();

        /* ---- skip/out GEMM + epilogue ---- */
        float* skb = g_skips + (size_t)b * CH * TLEN;
        float* hob = h_out + (size_t)b * CH * TLEN;
#pragma unroll 1
        for (int j = 0; j < 8; ++j) {
            float E0[4] = {0, 0, 0, 0}, E1[4] = {0, 0, 0, 0}, E2[4] = {0, 0, 0, 0};
            int tb = j * 16;
#pragma unroll
            for (int kk = 0; kk < 2; ++kk) {
                u32 bh[4], bm[4];
                ldmT_x4(bh, b2h_l4 + kk * 32 * 144 + tb);
                ldmT_x4(bm, b2m_l4 + kk * 32 * 144 + tb);
                mma16816(E0, Zh[2 * kk], bh);
                mma16816(E0, Zh[2 * kk + 1], bh + 2);
                mma16816(E1, Zh[2 * kk], bm);
                mma16816(E1, Zh[2 * kk + 1], bm + 2);
                mma16816(E2, Zm[2 * kk], bh);
                mma16816(E2, Zm[2 * kk + 1], bh + 2);
            }
            float e0 = E0[0] + E1[0] + E2[0] + bs0;
            float e1 = E0[1] + E1[1] + E2[1] + bs0;
            float e2 = E0[2] + E1[2] + E2[2] + bs1;
            float e3 = E0[3] + E1[3] + E2[3] + bs1;
            int t = t0 + j * 8 + lr * 2;
            if (r1 < 64) {
                float2* p0 = (float2*)(skb + (size_t)r1 * TLEN + t);
                float2* p1 = (float2*)(skb + (size_t)(r1 + 8) * TLEN + t);
                float2 v0 = {e0, e1}, v1 = {e2, e3};
                if (!first_layer) {
                    float2 o0 = *p0, o1 = *p1;
                    v0.x += o0.x; v0.y += o0.y; v1.x += o1.x; v1.y += o1.y;
                }
                *p0 = v0; *p1 = v1;
            } else {
                int c0 = r1 - 64, c1 = c0 + 8;
                float2 i0 = *(const float2*)(hb + (size_t)c0 * TLEN + t);
                float2 i1 = *(const float2*)(hb + (size_t)c1 * TLEN + t);
                float2 v0 = {e0 + i0.x, e1 + i0.y};
                float2 v1 = {e2 + i1.x, e3 + i1.y};
                *(float2*)(hob + (size_t)c0 * TLEN + t) = v0;
                *(float2*)(hob + (size_t)c1 * TLEN + t) = v1;
            }
        }
    }
}

/* ---------------- last: relu,1x1,relu,1x1 (FFMA2) ---------------- */
__global__ void __launch_bounds__(256) last_kernel(const float* __restrict__ l1b,
                                                   const float* __restrict__ l2b,
                                                   float* __restrict__ out) {
    extern __shared__ float sm[];
    float* w1 = sm;
    float* w2 = sm + 4096;
    float* sk = sm + 20480;
    float* o1 = sm + 24576;
    for (int i = threadIdx.x; i < 4096 / 4; i += blockDim.x)
        ((float4*)w1)[i] = ((const float4*)g_wl1T)[i];
    for (int i = threadIdx.x; i < 16384 / 4; i += blockDim.x)
        ((float4*)w2)[i] = ((const float4*)g_wl2T)[i];
    int to = threadIdx.x & 15, oo = threadIdx.x >> 4;
    int tb = to * 4;
    for (int tile = blockIdx.x; tile < NTILES; tile += gridDim.x) {
        int b = tile / (TLEN / TT), t0 = (tile % (TLEN / TT)) * TT;
        __syncthreads();
        const float* skb = g_skips + (size_t)b * CH * TLEN;
        for (int i = threadIdx.x; i < CH * (TT / 4); i += blockDim.x) {
            int c = i / (TT / 4), q = i % (TT / 4);
            float4 v = *(const float4*)&skb[c * TLEN + t0 + q * 4];
            v.x = fmaxf(v.x, 0.f); v.y = fmaxf(v.y, 0.f);
            v.z = fmaxf(v.z, 0.f); v.w = fmaxf(v.w, 0.f);
            ((float4*)sk)[c * (TT / 4) + q] = v;
        }
        __syncthreads();
        {
            int ob = oo * 4;
            u64 acc[2][4];
#pragma unroll
            for (int op = 0; op < 2; ++op) {
                u64 bv = pk2(l1b[ob + 2 * op], l1b[ob + 2 * op + 1]);
#pragma unroll
                for (int ti = 0; ti < 4; ++ti) acc[op][ti] = bv;
            }
#pragma unroll 2
            for (int c = 0; c < 64; ++c) {
                float4 xv4 = *(const float4*)(sk + c * TT + tb);
                u64 xv[4] = {dup2f(xv4.x), dup2f(xv4.y), dup2f(xv4.z), dup2f(xv4.w)};
                ulonglong2 wv = *(const ulonglong2*)(w1 + c * 64 + ob);
                u64 wp[2] = {wv.x, wv.y};
#pragma unroll
                for (int op = 0; op < 2; ++op)
#pragma unroll
                    for (int ti = 0; ti < 4; ++ti) fma2(acc[op][ti], wp[op], xv[ti]);
            }
#pragma unroll
            for (int op = 0; op < 2; ++op) {
                float lo[4], hi[4];
#pragma unroll
                for (int ti = 0; ti < 4; ++ti) upk(lo[ti], hi[ti], acc[op][ti]);
                float4 v0 = {fmaxf(lo[0], 0.f), fmaxf(lo[1], 0.f), fmaxf(lo[2], 0.f), fmaxf(lo[3], 0.f)};
                float4 v1 = {fmaxf(hi[0], 0.f), fmaxf(hi[1], 0.f), fmaxf(hi[2], 0.f), fmaxf(hi[3], 0.f)};
                *(float4*)(o1 + (ob + 2 * op) * TT + tb) = v0;
                *(float4*)(o1 + (ob + 2 * op + 1) * TT + tb) = v1;
            }
        }
        __syncthreads();
        float* ob_out = out + (size_t)b * 256 * TLEN;
#pragma unroll
        for (int half = 0; half < 2; ++half) {
            int ob2 = half * 128 + oo * 8;
            u64 acc[4][4];
#pragma unroll
            for (int op = 0; op < 4; ++op) {
                u64 bv = pk2(l2b[ob2 + 2 * op], l2b[ob2 + 2 * op + 1]);
#pragma unroll
                for (int ti = 0; ti < 4; ++ti) acc[op][ti] = bv;
            }
#pragma unroll 2
            for (int c = 0; c < 64; ++c) {
                float4 zv4 = *(const float4*)(o1 + c * TT + tb);
                u64 zv[4] = {dup2f(zv4.x), dup2f(zv4.y), dup2f(zv4.z), dup2f(zv4.w)};
                ulonglong2 wa = *(const ulonglong2*)(w2 + c * 256 + ob2);
                ulonglong2 wb = *(const ulonglong2*)(w2 + c * 256 + ob2 + 4);
                u64 wp[4] = {wa.x, wa.y, wb.x, wb.y};
#pragma unroll
                for (int op = 0; op < 4; ++op)
#pragma unroll
                    for (int ti = 0; ti < 4; ++ti) fma2(acc[op][ti], wp[op], zv[ti]);
            }
#pragma unroll
            for (int op = 0; op < 4; ++op) {
                float lo[4], hi[4];
#pragma unroll
                for (int ti = 0; ti < 4; ++ti) upk(lo[ti], hi[ti], acc[op][ti]);
                float4 v0 = {lo[0], lo[1], lo[2], lo[3]};
                float4 v1 = {hi[0], hi[1], hi[2], hi[3]};
                *(float4*)&ob_out[(ob2 + 2 * op) * TLEN + t0 + tb] = v0;
                *(float4*)&ob_out[(ob2 + 2 * op + 1) * TLEN + t0 + tb] = v1;
            }
        }
    }
}

/* --------------------------------------------------------------- */
extern "C" void kernel_launch(void* const* d_in, const int* in_sizes, int n_in,
                              void* d_out, int out_size) {
    const float* x        = (const float*)d_in[0];
    const float* c        = (const float*)d_in[1];
    const float* first_w  = (const float*)d_in[2];
    const float* first_b  = (const float*)d_in[3];
    const float* conv_w   = (const float*)d_in[4];
    const float* conv_b   = (const float*)d_in[5];
    const float* cond_w   = (const float*)d_in[6];
    const float* out_w    = (const float*)d_in[7];
    const float* out_b    = (const float*)d_in[8];
    const float* skip_w   = (const float*)d_in[9];
    const float* skip_b   = (const float*)d_in[10];
    const float* last1_w  = (const float*)d_in[11];
    const float* last1_b  = (const float*)d_in[12];
    const float* last2_w  = (const float*)d_in[13];
    const float* last2_b  = (const float*)d_in[14];
    const float* conv_in_w= (const float*)d_in[15];
    const float* up_w0    = (const float*)d_in[16];
    const float* up_w1    = (const float*)d_in[17];
    float* out = (float*)d_out;

    int dev = 0;
    cudaGetDevice(&dev);
    int sms = 148;
    cudaDeviceGetAttribute(&sms, cudaDevAttrMultiProcessorCount, dev);

    cudaFuncSetAttribute(first_kernel, cudaFuncAttributeMaxDynamicSharedMemorySize, 131072);
    cudaFuncSetAttribute(layer_kernel, cudaFuncAttributeMaxDynamicSharedMemorySize, SM_TOTAL);
    cudaFuncSetAttribute(last_kernel,  cudaFuncAttributeMaxDynamicSharedMemorySize, 114688);

    {
        int n = LAYERS * 128 * 104;
        prep_gate_kernel<<<(n + 255) / 256, 256>>>(conv_w, cond_w);
        n = LAYERS * 128 * 32;
        prep_wz_kernel<<<(n + 255) / 256, 256>>>(skip_w, out_w);
        prep_firstlast_kernel<<<(16384 + 4096 + 16384 + 255) / 256, 256>>>(
            first_w, last1_w, last2_w);
    }
    {
        int n1 = B_SZ * CCH * 400;
        convin_kernel<<<(n1 + 255) / 256, 256>>>(c, conv_in_w);
        int n2 = B_SZ * CCH * 4000;
        upsample1_kernel<<<(n2 + 255) / 256, 256>>>(up_w0);
        int n3 = B_SZ * CCH * TLEN;
        upsample2_kernel<<<(n3 + 255) / 256, 256>>>(up_w1);
    }

    first_kernel<<<sms, 256, 131072>>>(x, first_b);

    for (int l = 0; l < LAYERS; ++l) {
        int d = 1 << (l % 10);
        layer_kernel<<<sms, 256, SM_TOTAL>>>(l, d, l & 1, l == 0 ? 1 : 0,
                                             conv_b, skip_b, out_b);
    }

    last_kernel<<<sms, 256, 114688>>>(last1_b, last2_b, out);
}